// round 2
// baseline (speedup 1.0000x reference)
#include <cuda_runtime.h>
#include <cstdint>

// ---------------------------------------------------------------------------
// SpatialTemporalGridEncoder — B200 (sm_100a)
// inputs:      [B,4]  fp32   (d_in[0])
// sembeddings: [6328848,2]   (d_in[1])  spatial 3D multires grid, 16 levels
// tembeddings: [7736064,2]   (d_in[2])  temporal 4D multires grid, 16 levels
// membeddings: [128^3]       (d_in[3])  dense mask grid
// out:         [B,32] fp32
// ---------------------------------------------------------------------------

namespace enc {

constexpr unsigned P1 = 2654435761u;
constexpr unsigned P2 = 805459861u;
constexpr unsigned P3 = 3674653429u;
constexpr unsigned HMASK = 524287u;   // hash levels: hashmap_size = 2^19

// grid = ceil(16 * 1.447^l) + 1  (spatial xyz; also temporal xyz dims)
__device__ constexpr int SGRID[16] =
    {17,25,35,50,72,103,148,214,309,446,645,933,1350,1952,2824,4086};
// temporal t grid = ceil(16 * 1.15^l) + 1
__device__ constexpr int TGRID[16] =
    {17,20,23,26,29,34,39,44,50,58,66,76,87,100,115,132};
// row offsets (params rounded up to 8, capped at 2^19)
__device__ constexpr int SOFF[16] =
    {0,4920,20552,63432,188432,561680,1085968,1610256,2134544,
     2658832,3183120,3707408,4231696,4755984,5280272,5804560};
__device__ constexpr int TOFF[16] =
    {0,83528,396032,920320,1444608,1968896,2493184,3017472,3541760,
     4066048,4590336,5114624,5638912,6163200,6687488,7211776};
// spatial: hash for l>=5 ; temporal: hash for l>=2

// ---------------- 3D interp (spatial levels) ----------------
template<bool HASH>
__device__ __forceinline__ void interp3(const float2* __restrict__ tab,
                                        float x, float y, float z, int g,
                                        float& r0, float& r1)
{
    const float gm1 = (float)(g - 1);
    float px = x * gm1, py = y * gm1, pz = z * gm1;
    float fx0 = floorf(px), fy0 = floorf(py), fz0 = floorf(pz);
    float fx = px - fx0, fy = py - fy0, fz = pz - fz0;
    int ix0 = min(max((int)fx0, 0), g - 1);
    int iy0 = min(max((int)fy0, 0), g - 1);
    int iz0 = min(max((int)fz0, 0), g - 1);
    int ix1 = min(ix0 + 1, g - 1);
    int iy1 = min(iy0 + 1, g - 1);
    int iz1 = min(iz0 + 1, g - 1);

    unsigned ox[2], oy[2], oz[2];
    if (HASH) {
        ox[0] = (unsigned)ix0;        ox[1] = (unsigned)ix1;
        oy[0] = (unsigned)iy0 * P1;   oy[1] = (unsigned)iy1 * P1;
        oz[0] = (unsigned)iz0 * P2;   oz[1] = (unsigned)iz1 * P2;
    } else {
        const unsigned s1 = (unsigned)g, s2 = s1 * s1;
        ox[0] = (unsigned)ix0;        ox[1] = (unsigned)ix1;
        oy[0] = (unsigned)iy0 * s1;   oy[1] = (unsigned)iy1 * s1;
        oz[0] = (unsigned)iz0 * s2;   oz[1] = (unsigned)iz1 * s2;
    }
    float wx[2] = {1.f - fx, fx};
    float wy[2] = {1.f - fy, fy};
    float wz[2] = {1.f - fz, fz};
    float wxy[4];
#pragma unroll
    for (int c = 0; c < 4; c++) wxy[c] = wx[c & 1] * wy[(c >> 1) & 1];

    // issue all 8 gathers first (max MLP), then reduce
    float2 v[8];
#pragma unroll
    for (int c = 0; c < 8; c++) {
        unsigned idx;
        if (HASH) idx = (ox[c & 1] ^ oy[(c >> 1) & 1] ^ oz[(c >> 2) & 1]) & HMASK;
        else      idx =  ox[c & 1] + oy[(c >> 1) & 1] + oz[(c >> 2) & 1];
        v[c] = __ldg(tab + idx);
    }
    float a0 = 0.f, a1 = 0.f;
#pragma unroll
    for (int c = 0; c < 8; c++) {
        float w = wxy[c & 3] * wz[(c >> 2) & 1];
        a0 = fmaf(w, v[c].x, a0);
        a1 = fmaf(w, v[c].y, a1);
    }
    r0 = a0; r1 = a1;
}

// ---------------- 4D interp (temporal levels) ----------------
template<bool HASH>
__device__ __forceinline__ void interp4(const float2* __restrict__ tab,
                                        float x, float y, float z, float t,
                                        int g, int gt,
                                        float& r0, float& r1)
{
    const float gm1 = (float)(g - 1);
    const float tm1 = (float)(gt - 1);
    float px = x * gm1, py = y * gm1, pz = z * gm1, pt = t * tm1;
    float fx0 = floorf(px), fy0 = floorf(py), fz0 = floorf(pz), ft0 = floorf(pt);
    float fx = px - fx0, fy = py - fy0, fz = pz - fz0, ft = pt - ft0;
    int ix0 = min(max((int)fx0, 0), g - 1);
    int iy0 = min(max((int)fy0, 0), g - 1);
    int iz0 = min(max((int)fz0, 0), g - 1);
    int it0 = min(max((int)ft0, 0), gt - 1);
    int ix1 = min(ix0 + 1, g - 1);
    int iy1 = min(iy0 + 1, g - 1);
    int iz1 = min(iz0 + 1, g - 1);
    int it1 = min(it0 + 1, gt - 1);

    unsigned ox[2], oy[2], oz[2], ot[2];
    if (HASH) {
        ox[0] = (unsigned)ix0;        ox[1] = (unsigned)ix1;
        oy[0] = (unsigned)iy0 * P1;   oy[1] = (unsigned)iy1 * P1;
        oz[0] = (unsigned)iz0 * P2;   oz[1] = (unsigned)iz1 * P2;
        ot[0] = (unsigned)it0 * P3;   ot[1] = (unsigned)it1 * P3;
    } else {
        const unsigned s1 = (unsigned)g, s2 = s1 * s1, s3 = s2 * s1;
        ox[0] = (unsigned)ix0;        ox[1] = (unsigned)ix1;
        oy[0] = (unsigned)iy0 * s1;   oy[1] = (unsigned)iy1 * s1;
        oz[0] = (unsigned)iz0 * s2;   oz[1] = (unsigned)iz1 * s2;
        ot[0] = (unsigned)it0 * s3;   ot[1] = (unsigned)it1 * s3;
    }
    float wx[2] = {1.f - fx, fx};
    float wy[2] = {1.f - fy, fy};
    float wz[2] = {1.f - fz, fz};
    float wt[2] = {1.f - ft, ft};
    float wxy[4], wzt[4];
#pragma unroll
    for (int c = 0; c < 4; c++) {
        wxy[c] = wx[c & 1] * wy[(c >> 1) & 1];
        wzt[c] = wz[c & 1] * wt[(c >> 1) & 1];
    }

    float2 v[16];
#pragma unroll
    for (int c = 0; c < 16; c++) {
        unsigned idx;
        if (HASH) idx = (ox[c & 1] ^ oy[(c >> 1) & 1] ^ oz[(c >> 2) & 1] ^ ot[(c >> 3) & 1]) & HMASK;
        else      idx =  ox[c & 1] + oy[(c >> 1) & 1] + oz[(c >> 2) & 1] + ot[(c >> 3) & 1];
        v[c] = __ldg(tab + idx);
    }
    float a0 = 0.f, a1 = 0.f;
#pragma unroll
    for (int c = 0; c < 16; c++) {
        float w = wxy[c & 3] * wzt[(c >> 2) & 3];
        a0 = fmaf(w, v[c].x, a0);
        a1 = fmaf(w, v[c].y, a1);
    }
    r0 = a0; r1 = a1;
}

} // namespace enc

__global__ void __launch_bounds__(256)
stge_kernel(const float4* __restrict__ inp,
            const float2* __restrict__ semb,
            const float2* __restrict__ temb,
            const float*  __restrict__ memb,
            float* __restrict__ out,
            int B)
{
    using namespace enc;
    int b = blockIdx.x * 256 + threadIdx.x;
    if (b >= B) return;

    float4 p = __ldg(inp + b);
    const float x = p.x, y = p.y, z = p.z, t = p.w;

    // ---------------- mask: dense 128^3 grid, C=1 ----------------
    float m;
    {
        float px = x * 127.f, py = y * 127.f, pz = z * 127.f;
        float fx0 = floorf(px), fy0 = floorf(py), fz0 = floorf(pz);
        float fx = px - fx0, fy = py - fy0, fz = pz - fz0;
        int ix0 = min(max((int)fx0, 0), 127);
        int iy0 = min(max((int)fy0, 0), 127);
        int iz0 = min(max((int)fz0, 0), 127);
        int ix1 = min(ix0 + 1, 127);
        int iy1 = min(iy0 + 1, 127);
        int iz1 = min(iz0 + 1, 127);
        int xo[2] = {ix0, ix1};
        int yo[2] = {iy0 * 128, iy1 * 128};
        int zo[2] = {iz0 * 16384, iz1 * 16384};
        float wx[2] = {1.f - fx, fx};
        float wy[2] = {1.f - fy, fy};
        float wz[2] = {1.f - fz, fz};
        float mv[8];
#pragma unroll
        for (int c = 0; c < 8; c++)
            mv[c] = __ldg(memb + xo[c & 1] + yo[(c >> 1) & 1] + zo[(c >> 2) & 1]);
        float mr = 0.f;
#pragma unroll
        for (int c = 0; c < 8; c++) {
            float w = wx[c & 1] * wy[(c >> 1) & 1] * wz[(c >> 2) & 1];
            mr = fmaf(w, mv[c], mr);
        }
        m = 1.f / (1.f + __expf(-mr));
    }
    const float om = 1.f - m;

    float4* o4 = reinterpret_cast<float4*>(out) + (size_t)b * 8;

    // process 2 levels at a time; store a float4 per pair to keep regs low
#define DO_PAIR(L0)                                                            \
    {                                                                          \
        constexpr int lA = (L0), lB = (L0) + 1;                                \
        float sA0, sA1, tA0, tA1, sB0, sB1, tB0, tB1;                          \
        interp3<(lA >= 5)>(semb + SOFF[lA], x, y, z, SGRID[lA], sA0, sA1);     \
        interp4<(lA >= 2)>(temb + TOFF[lA], x, y, z, t, SGRID[lA], TGRID[lA],  \
                           tA0, tA1);                                          \
        interp3<(lB >= 5)>(semb + SOFF[lB], x, y, z, SGRID[lB], sB0, sB1);     \
        interp4<(lB >= 2)>(temb + TOFF[lB], x, y, z, t, SGRID[lB], TGRID[lB],  \
                           tB0, tB1);                                          \
        o4[(L0) / 2] = make_float4(fmaf(m, sA0, om * tA0),                     \
                                   fmaf(m, sA1, om * tA1),                     \
                                   fmaf(m, sB0, om * tB0),                     \
                                   fmaf(m, sB1, om * tB1));                    \
    }

    DO_PAIR(0)  DO_PAIR(2)  DO_PAIR(4)  DO_PAIR(6)
    DO_PAIR(8)  DO_PAIR(10) DO_PAIR(12) DO_PAIR(14)
#undef DO_PAIR
}

extern "C" void kernel_launch(void* const* d_in, const int* in_sizes, int n_in,
                              void* d_out, int out_size)
{
    const float4* inp  = (const float4*)d_in[0];
    const float2* semb = (const float2*)d_in[1];
    const float2* temb = (const float2*)d_in[2];
    const float*  memb = (const float*)d_in[3];
    float* out = (float*)d_out;

    int B = in_sizes[0] / 4;
    int blocks = (B + 255) / 256;
    stge_kernel<<<blocks, 256>>>(inp, semb, temb, memb, out, B);
}

// round 5
// speedup vs baseline: 1.1958x; 1.1958x over previous
#include <cuda_runtime.h>
#include <cstdint>

// ---------------------------------------------------------------------------
// SpatialTemporalGridEncoder — B200 (sm_100a)
// Round 5 (= Round 3/4 resubmit; both died to container-infra failures before
// launch): fuse x-adjacent corner pairs into aligned float4 gathers when the
// two hash/dense indices form {base, base+1} (test: (i0^i1)==1). Cuts L1tex
// wavefronts ~25% and L2 sectors ~15-20% on the gather-bound hot path.
// Baseline to beat: 610.4 us (lts=82.5%, l1tex=89.3%, issue=11.6%).
// ---------------------------------------------------------------------------

namespace enc {

constexpr unsigned P1 = 2654435761u;
constexpr unsigned P2 = 805459861u;
constexpr unsigned P3 = 3674653429u;
constexpr unsigned HMASK = 524287u;   // hash levels: hashmap_size = 2^19

__device__ constexpr int SGRID[16] =
    {17,25,35,50,72,103,148,214,309,446,645,933,1350,1952,2824,4086};
__device__ constexpr int TGRID[16] =
    {17,20,23,26,29,34,39,44,50,58,66,76,87,100,115,132};
__device__ constexpr int SOFF[16] =
    {0,4920,20552,63432,188432,561680,1085968,1610256,2134544,
     2658832,3183120,3707408,4231696,4755984,5280272,5804560};
__device__ constexpr int TOFF[16] =
    {0,83528,396032,920320,1444608,1968896,2493184,3017472,3541760,
     4066048,4590336,5114624,5638912,6163200,6687488,7211776};
// spatial: hash for l>=5 ; temporal: hash for l>=2

// fetch the (x0, x1=x0+1) corner pair; fuse into one LDG.128 when the two
// indices are {base, base+1} (always 16B-aligned since base is even).
__device__ __forceinline__ void fetch_pair(const float2* __restrict__ tab,
                                           unsigned i0, unsigned i1,
                                           float2& v0, float2& v1)
{
    const bool fused = ((i0 ^ i1) == 1u);
    const bool swap  = (i0 & 1u);
    if (fused) {
        const float4 q = __ldg(reinterpret_cast<const float4*>(tab + (i0 & ~1u)));
        v0 = swap ? make_float2(q.z, q.w) : make_float2(q.x, q.y);
        v1 = swap ? make_float2(q.x, q.y) : make_float2(q.z, q.w);
    } else {
        v0 = __ldg(tab + i0);
        v1 = __ldg(tab + i1);
    }
}

// ---------------- 3D interp (spatial levels) ----------------
template<bool HASH>
__device__ __forceinline__ void interp3(const float2* __restrict__ tab,
                                        float x, float y, float z, int g,
                                        float& r0, float& r1)
{
    const float gm1 = (float)(g - 1);
    float px = x * gm1, py = y * gm1, pz = z * gm1;
    float fx0 = floorf(px), fy0 = floorf(py), fz0 = floorf(pz);
    float fx = px - fx0, fy = py - fy0, fz = pz - fz0;
    unsigned ix0 = (unsigned)(int)fx0;     // x in [0,1) -> no clamping needed
    unsigned iy0 = (unsigned)(int)fy0;
    unsigned iz0 = (unsigned)(int)fz0;
    unsigned ix1 = ix0 + 1;

    unsigned oy[2], oz[2];
    if (HASH) {
        oy[0] = iy0 * P1;     oy[1] = (iy0 + 1) * P1;
        oz[0] = iz0 * P2;     oz[1] = (iz0 + 1) * P2;
    } else {
        const unsigned s1 = (unsigned)g, s2 = s1 * s1;
        oy[0] = iy0 * s1;     oy[1] = oy[0] + s1;
        oz[0] = iz0 * s2;     oz[1] = oz[0] + s2;
    }
    float wy[2] = {1.f - fy, fy};
    float wz[2] = {1.f - fz, fz};
    float wyz[4];
#pragma unroll
    for (int c = 0; c < 4; c++) wyz[c] = wy[c & 1] * wz[(c >> 1) & 1];

    float2 v0[4], v1[4];
#pragma unroll
    for (int c = 0; c < 4; c++) {
        unsigned i0, i1;
        if (HASH) {
            unsigned h = oy[c & 1] ^ oz[(c >> 1) & 1];
            i0 = (ix0 ^ h) & HMASK;
            i1 = (ix1 ^ h) & HMASK;
        } else {
            unsigned h = oy[c & 1] + oz[(c >> 1) & 1];
            i0 = ix0 + h;
            i1 = ix1 + h;
        }
        fetch_pair(tab, i0, i1, v0[c], v1[c]);
    }
    const float wx1 = fx, wx0 = 1.f - fx;
    float a0 = 0.f, a1 = 0.f;
#pragma unroll
    for (int c = 0; c < 4; c++) {
        float m0 = fmaf(wx0, v0[c].x, wx1 * v1[c].x);
        float m1 = fmaf(wx0, v0[c].y, wx1 * v1[c].y);
        a0 = fmaf(wyz[c], m0, a0);
        a1 = fmaf(wyz[c], m1, a1);
    }
    r0 = a0; r1 = a1;
}

// ---------------- 4D interp (temporal levels) ----------------
template<bool HASH>
__device__ __forceinline__ void interp4(const float2* __restrict__ tab,
                                        float x, float y, float z, float t,
                                        int g, int gt,
                                        float& r0, float& r1)
{
    const float gm1 = (float)(g - 1);
    const float tm1 = (float)(gt - 1);
    float px = x * gm1, py = y * gm1, pz = z * gm1, pt = t * tm1;
    float fx0 = floorf(px), fy0 = floorf(py), fz0 = floorf(pz), ft0 = floorf(pt);
    float fx = px - fx0, fy = py - fy0, fz = pz - fz0, ft = pt - ft0;
    unsigned ix0 = (unsigned)(int)fx0;
    unsigned iy0 = (unsigned)(int)fy0;
    unsigned iz0 = (unsigned)(int)fz0;
    unsigned it0 = (unsigned)(int)ft0;
    unsigned ix1 = ix0 + 1;

    unsigned oy[2], oz[2], ot[2];
    if (HASH) {
        oy[0] = iy0 * P1;   oy[1] = (iy0 + 1) * P1;
        oz[0] = iz0 * P2;   oz[1] = (iz0 + 1) * P2;
        ot[0] = it0 * P3;   ot[1] = (it0 + 1) * P3;
    } else {
        const unsigned s1 = (unsigned)g, s2 = s1 * s1, s3 = s2 * s1;
        oy[0] = iy0 * s1;   oy[1] = oy[0] + s1;
        oz[0] = iz0 * s2;   oz[1] = oz[0] + s2;
        ot[0] = it0 * s3;   ot[1] = ot[0] + s3;
    }
    float wy[2] = {1.f - fy, fy};
    float wz[2] = {1.f - fz, fz};
    float wt[2] = {1.f - ft, ft};
    float wyzt[8];
#pragma unroll
    for (int c = 0; c < 8; c++)
        wyzt[c] = wy[c & 1] * wz[(c >> 1) & 1] * wt[(c >> 2) & 1];

    float2 v0[8], v1[8];
#pragma unroll
    for (int c = 0; c < 8; c++) {
        unsigned i0, i1;
        if (HASH) {
            unsigned h = oy[c & 1] ^ oz[(c >> 1) & 1] ^ ot[(c >> 2) & 1];
            i0 = (ix0 ^ h) & HMASK;
            i1 = (ix1 ^ h) & HMASK;
        } else {
            unsigned h = oy[c & 1] + oz[(c >> 1) & 1] + ot[(c >> 2) & 1];
            i0 = ix0 + h;
            i1 = ix1 + h;
        }
        fetch_pair(tab, i0, i1, v0[c], v1[c]);
    }
    const float wx1 = fx, wx0 = 1.f - fx;
    float a0 = 0.f, a1 = 0.f;
#pragma unroll
    for (int c = 0; c < 8; c++) {
        float m0 = fmaf(wx0, v0[c].x, wx1 * v1[c].x);
        float m1 = fmaf(wx0, v0[c].y, wx1 * v1[c].y);
        a0 = fmaf(wyzt[c], m0, a0);
        a1 = fmaf(wyzt[c], m1, a1);
    }
    r0 = a0; r1 = a1;
}

} // namespace enc

__global__ void __launch_bounds__(256)
stge_kernel(const float4* __restrict__ inp,
            const float2* __restrict__ semb,
            const float2* __restrict__ temb,
            const float*  __restrict__ memb,
            float* __restrict__ out,
            int B)
{
    using namespace enc;
    int b = blockIdx.x * 256 + threadIdx.x;
    if (b >= B) return;

    float4 p = __ldg(inp + b);
    const float x = p.x, y = p.y, z = p.z, t = p.w;

    // ---------------- mask: dense 128^3 grid, C=1 ----------------
    float m;
    {
        float px = x * 127.f, py = y * 127.f, pz = z * 127.f;
        float fx0 = floorf(px), fy0 = floorf(py), fz0 = floorf(pz);
        float fx = px - fx0, fy = py - fy0, fz = pz - fz0;
        unsigned ix0 = (unsigned)(int)fx0;
        unsigned iy0 = (unsigned)(int)fy0;
        unsigned iz0 = (unsigned)(int)fz0;
        unsigned yo[2] = {iy0 * 128u, (iy0 + 1) * 128u};
        unsigned zo[2] = {iz0 * 16384u, (iz0 + 1) * 16384u};
        float wy[2] = {1.f - fy, fy};
        float wz[2] = {1.f - fz, fz};
        float v0[4], v1[4];
#pragma unroll
        for (int c = 0; c < 4; c++) {
            unsigned i0 = ix0 + yo[c & 1] + zo[(c >> 1) & 1];
            if (!(i0 & 1u)) {
                float2 q = __ldg(reinterpret_cast<const float2*>(memb + i0));
                v0[c] = q.x; v1[c] = q.y;
            } else {
                v0[c] = __ldg(memb + i0);
                v1[c] = __ldg(memb + i0 + 1);
            }
        }
        float mr = 0.f;
        const float wx1 = fx, wx0 = 1.f - fx;
#pragma unroll
        for (int c = 0; c < 4; c++) {
            float mv = fmaf(wx0, v0[c], wx1 * v1[c]);
            mr = fmaf(wy[c & 1] * wz[(c >> 1) & 1], mv, mr);
        }
        m = 1.f / (1.f + __expf(-mr));
    }
    const float om = 1.f - m;

    float4* o4 = reinterpret_cast<float4*>(out) + (size_t)b * 8;

#define DO_PAIR(L0)                                                            \
    {                                                                          \
        constexpr int lA = (L0), lB = (L0) + 1;                                \
        float sA0, sA1, tA0, tA1, sB0, sB1, tB0, tB1;                          \
        interp3<(lA >= 5)>(semb + SOFF[lA], x, y, z, SGRID[lA], sA0, sA1);     \
        interp4<(lA >= 2)>(temb + TOFF[lA], x, y, z, t, SGRID[lA], TGRID[lA],  \
                           tA0, tA1);                                          \
        interp3<(lB >= 5)>(semb + SOFF[lB], x, y, z, SGRID[lB], sB0, sB1);     \
        interp4<(lB >= 2)>(temb + TOFF[lB], x, y, z, t, SGRID[lB], TGRID[lB],  \
                           tB0, tB1);                                          \
        o4[(L0) / 2] = make_float4(fmaf(m, sA0, om * tA0),                     \
                                   fmaf(m, sA1, om * tA1),                     \
                                   fmaf(m, sB0, om * tB0),                     \
                                   fmaf(m, sB1, om * tB1));                    \
    }

    DO_PAIR(0)  DO_PAIR(2)  DO_PAIR(4)  DO_PAIR(6)
    DO_PAIR(8)  DO_PAIR(10) DO_PAIR(12) DO_PAIR(14)
#undef DO_PAIR
}

extern "C" void kernel_launch(void* const* d_in, const int* in_sizes, int n_in,
                              void* d_out, int out_size)
{
    const float4* inp  = (const float4*)d_in[0];
    const float2* semb = (const float2*)d_in[1];
    const float2* temb = (const float2*)d_in[2];
    const float*  memb = (const float*)d_in[3];
    float* out = (float*)d_out;

    int B = in_sizes[0] / 4;
    int blocks = (B + 255) / 256;
    stge_kernel<<<blocks, 256>>>(inp, semb, temb, memb, out, B);
}